// round 1
// baseline (speedup 1.0000x reference)
#include <cuda_runtime.h>
#include <math.h>

#define BB  4
#define TT  2048
#define DD  1024
#define HH  16
#define HDD 64
#define BHH (BB*HH)

// QKV scratch in head-split layout: [3][B*H][T][HD]
__device__ float g_qkv[3ULL * BHH * TT * HDD];

// ---------------------------------------------------------------------------
// QKV projection: C = X @ W + b, written head-split. z selects Q/K/V.
// 128x128 output tile, BK=8, 256 threads, 8x8 per thread.
// ---------------------------------------------------------------------------
__global__ void __launch_bounds__(256) qkv_gemm_kernel(
    const float* __restrict__ X,
    const float* __restrict__ Wq, const float* __restrict__ bq,
    const float* __restrict__ Wk, const float* __restrict__ bk,
    const float* __restrict__ Wv, const float* __restrict__ bv)
{
    const int z = blockIdx.z;
    const float* Wm   = (z == 0) ? Wq : (z == 1) ? Wk : Wv;
    const float* bias = (z == 0) ? bq : (z == 1) ? bk : bv;

    __shared__ float As[8][128];   // As[k][m]
    __shared__ float Bs[8][128];   // Bs[k][n]

    const int tid = threadIdx.x;
    const int bn = blockIdx.x;     // N tile (8 tiles)
    const int bm = blockIdx.y;     // M tile (64 tiles)
    const int tr = tid >> 4;       // 0..15
    const int tc = tid & 15;       // 0..15

    const int arow = tid >> 1;          // 0..127
    const int acol = (tid & 1) * 4;     // 0 or 4
    const int brow = tid >> 5;          // 0..7
    const int bcol = (tid & 31) * 4;    // 0..124

    const float* Aptr = X  + (size_t)(bm * 128 + arow) * DD + acol;
    const float* Bptr = Wm + (size_t)brow * DD + bn * 128 + bcol;

    float acc[8][8] = {};

    for (int kk = 0; kk < DD; kk += 8) {
        float4 av  = *(const float4*)(Aptr + kk);
        float4 bv4 = *(const float4*)(Bptr + (size_t)kk * DD);
        __syncthreads();
        As[acol + 0][arow] = av.x;
        As[acol + 1][arow] = av.y;
        As[acol + 2][arow] = av.z;
        As[acol + 3][arow] = av.w;
        *(float4*)(&Bs[brow][bcol]) = bv4;
        __syncthreads();
        #pragma unroll
        for (int k = 0; k < 8; k++) {
            float a[8], b[8];
            #pragma unroll
            for (int i = 0; i < 8; i++) a[i] = As[k][tr * 8 + i];
            #pragma unroll
            for (int j = 0; j < 8; j++) b[j] = Bs[k][tc * 8 + j];
            #pragma unroll
            for (int i = 0; i < 8; i++)
                #pragma unroll
                for (int j = 0; j < 8; j++)
                    acc[i][j] = fmaf(a[i], b[j], acc[i][j]);
        }
    }

    // Epilogue: write into head-split scratch [z][b*H+h][t][hd]
    const int bidx = bm >> 4;   // 128-row tiles: 16 tiles per batch (T=2048)
    #pragma unroll
    for (int i = 0; i < 8; i++) {
        int m = bm * 128 + tr * 8 + i;
        int t = m & (TT - 1);
        #pragma unroll
        for (int j = 0; j < 8; j++) {
            int col = bn * 128 + tc * 8 + j;
            int h  = col >> 6;
            int hd = col & 63;
            g_qkv[(((size_t)z * BHH + bidx * HH + h) * TT + t) * HDD + hd] =
                acc[i][j] + bias[col];
        }
    }
}

// ---------------------------------------------------------------------------
// Flash attention: one block = one (b,h) and 64 query rows.
// Loops over 32-key tiles with online softmax. O accumulated in registers.
// Thread layout: 16x16; each thread owns 4 query rows.
//   S pass:  s[4 rows][2 key cols]   (64x32 S tile)
//   PV pass: o[4 rows][4 hd cols]    (64x64 O tile)
// ---------------------------------------------------------------------------
__global__ void __launch_bounds__(256) attn_kernel(float* __restrict__ out)
{
    __shared__ float Qs[64 * 64];    // Q tile, pre-scaled, stride 64
    __shared__ float KPs[32 * 65];   // K tile (stride 65), reused as P (stride 32)
    __shared__ float Vs[32 * 64];    // V tile, stride 64

    const int tid = threadIdx.x;
    const int ty = tid >> 4;   // 0..15 -> query rows ty*4..ty*4+3
    const int tx = tid & 15;   // 0..15
    const int bh = blockIdx.y;
    const int q0 = blockIdx.x * 64;

    const float* Qg = g_qkv + ((size_t)(0 * BHH + bh) * TT + q0) * HDD;
    const float* Kg = g_qkv + ((size_t)(1 * BHH + bh) * TT) * HDD;
    const float* Vg = g_qkv + ((size_t)(2 * BHH + bh) * TT) * HDD;

    const float scale = 0.125f;   // 1/sqrt(64)

    // Load Q tile once, pre-scaled.
    for (int i = tid; i < 64 * 16; i += 256) {
        int r = i >> 4, c4 = (i & 15) * 4;
        float4 v = *(const float4*)(Qg + (size_t)r * 64 + c4);
        Qs[r * 64 + c4 + 0] = v.x * scale;
        Qs[r * 64 + c4 + 1] = v.y * scale;
        Qs[r * 64 + c4 + 2] = v.z * scale;
        Qs[r * 64 + c4 + 3] = v.w * scale;
    }

    float m_[4], l_[4];
    float o[4][4] = {};
    #pragma unroll
    for (int i = 0; i < 4; i++) { m_[i] = -1e30f; l_[i] = 0.f; }

    for (int jt = 0; jt < TT / 32; jt++) {
        __syncthreads();   // prior PV pass done; safe to overwrite KPs/Vs
        // Load K tile (stride 65) and V tile (stride 64)
        for (int i = tid; i < 32 * 16; i += 256) {
            int r = i >> 4, c4 = (i & 15) * 4;
            float4 kv = *(const float4*)(Kg + (size_t)(jt * 32 + r) * 64 + c4);
            KPs[r * 65 + c4 + 0] = kv.x;
            KPs[r * 65 + c4 + 1] = kv.y;
            KPs[r * 65 + c4 + 2] = kv.z;
            KPs[r * 65 + c4 + 3] = kv.w;
            float4 vv = *(const float4*)(Vg + (size_t)(jt * 32 + r) * 64 + c4);
            *(float4*)(&Vs[r * 64 + c4]) = vv;
        }
        __syncthreads();

        // S = (Q*scale) @ K^T : 64x32 tile, 4x2 per thread
        float s[4][2] = {};
        #pragma unroll 8
        for (int d = 0; d < 64; d++) {
            float q[4], k2[2];
            #pragma unroll
            for (int i = 0; i < 4; i++) q[i] = Qs[(ty * 4 + i) * 64 + d];
            #pragma unroll
            for (int j = 0; j < 2; j++) k2[j] = KPs[(tx * 2 + j) * 65 + d];
            #pragma unroll
            for (int i = 0; i < 4; i++)
                #pragma unroll
                for (int j = 0; j < 2; j++)
                    s[i][j] = fmaf(q[i], k2[j], s[i][j]);
        }

        // Online softmax: row stats shared by 16 tx threads (shfl width 16)
        float p[4][2];
        #pragma unroll
        for (int i = 0; i < 4; i++) {
            float mx = fmaxf(s[i][0], s[i][1]);
            #pragma unroll
            for (int off = 8; off > 0; off >>= 1)
                mx = fmaxf(mx, __shfl_xor_sync(0xffffffffu, mx, off, 16));
            float mnew  = fmaxf(m_[i], mx);
            float alpha = __expf(m_[i] - mnew);
            float ps = 0.f;
            #pragma unroll
            for (int j = 0; j < 2; j++) {
                p[i][j] = __expf(s[i][j] - mnew);
                ps += p[i][j];
            }
            #pragma unroll
            for (int off = 8; off > 0; off >>= 1)
                ps += __shfl_xor_sync(0xffffffffu, ps, off, 16);
            l_[i] = l_[i] * alpha + ps;
            m_[i] = mnew;
            #pragma unroll
            for (int j = 0; j < 4; j++) o[i][j] *= alpha;
        }

        __syncthreads();   // everyone done reading K rows before P overwrite
        // Write P (64x32, stride 32) into KPs
        #pragma unroll
        for (int i = 0; i < 4; i++)
            #pragma unroll
            for (int j = 0; j < 2; j++)
                KPs[(ty * 4 + i) * 32 + tx * 2 + j] = p[i][j];
        __syncthreads();

        // O += P @ V : 64x64, 4x4 per thread
        #pragma unroll 4
        for (int k = 0; k < 32; k++) {
            float pp[4], vv[4];
            #pragma unroll
            for (int i = 0; i < 4; i++) pp[i] = KPs[(ty * 4 + i) * 32 + k];
            #pragma unroll
            for (int j = 0; j < 4; j++) vv[j] = Vs[k * 64 + tx * 4 + j];
            #pragma unroll
            for (int i = 0; i < 4; i++)
                #pragma unroll
                for (int j = 0; j < 4; j++)
                    o[i][j] = fmaf(pp[i], vv[j], o[i][j]);
        }
    }

    // Normalize and write out in [B][T][D] layout
    const int b = bh >> 4, h = bh & 15;
    #pragma unroll
    for (int i = 0; i < 4; i++) {
        float inv = 1.0f / l_[i];
        int t = q0 + ty * 4 + i;
        #pragma unroll
        for (int j = 0; j < 4; j++) {
            int col = h * 64 + tx * 4 + j;
            out[((size_t)b * TT + t) * DD + col] = o[i][j] * inv;
        }
    }
}

// ---------------------------------------------------------------------------
extern "C" void kernel_launch(void* const* d_in, const int* in_sizes, int n_in,
                              void* d_out, int out_size)
{
    const float* x  = (const float*)d_in[0];
    const float* Wq = (const float*)d_in[1];
    const float* bq = (const float*)d_in[2];
    const float* Wk = (const float*)d_in[3];
    const float* bk = (const float*)d_in[4];
    const float* Wv = (const float*)d_in[5];
    const float* bv = (const float*)d_in[6];
    float* out = (float*)d_out;

    // QKV projections: grid (N/128, M/128, 3)
    qkv_gemm_kernel<<<dim3(DD / 128, BB * TT / 128, 3), 256>>>(
        x, Wq, bq, Wk, bk, Wv, bv);

    // Attention: grid (T/64 query tiles, B*H heads)
    attn_kernel<<<dim3(TT / 64, BHH), 256>>>(out);
}

// round 2
// speedup vs baseline: 1.0006x; 1.0006x over previous
#include <cuda_runtime.h>
#include <math.h>

#define BB  4
#define TT  2048
#define DD  1024
#define HH  16
#define HDD 64
#define BHH (BB*HH)

// QKV scratch in head-split layout: [3][B*H][T][HD]
__device__ float g_qkv[3ULL * BHH * TT * HDD];

// ---------------------------------------------------------------------------
// QKV projection: C = X @ W + b, written head-split. z selects Q/K/V.
// 128x128 output tile, BK=8, 256 threads, 8x8 per thread.
// ---------------------------------------------------------------------------
__global__ void __launch_bounds__(256) qkv_gemm_kernel(
    const float* __restrict__ X,
    const float* __restrict__ Wq, const float* __restrict__ bq,
    const float* __restrict__ Wk, const float* __restrict__ bk,
    const float* __restrict__ Wv, const float* __restrict__ bv)
{
    const int z = blockIdx.z;
    const float* Wm   = (z == 0) ? Wq : (z == 1) ? Wk : Wv;
    const float* bias = (z == 0) ? bq : (z == 1) ? bk : bv;

    __shared__ float As[8][128];   // As[k][m]
    __shared__ float Bs[8][128];   // Bs[k][n]

    const int tid = threadIdx.x;
    const int bn = blockIdx.x;     // N tile (8 tiles)
    const int bm = blockIdx.y;     // M tile (64 tiles)
    const int tr = tid >> 4;       // 0..15
    const int tc = tid & 15;       // 0..15

    const int arow = tid >> 1;          // 0..127
    const int acol = (tid & 1) * 4;     // 0 or 4
    const int brow = tid >> 5;          // 0..7
    const int bcol = (tid & 31) * 4;    // 0..124

    const float* Aptr = X  + (size_t)(bm * 128 + arow) * DD + acol;
    const float* Bptr = Wm + (size_t)brow * DD + bn * 128 + bcol;

    float acc[8][8] = {};

    for (int kk = 0; kk < DD; kk += 8) {
        float4 av  = *(const float4*)(Aptr + kk);
        float4 bv4 = *(const float4*)(Bptr + (size_t)kk * DD);
        __syncthreads();
        As[acol + 0][arow] = av.x;
        As[acol + 1][arow] = av.y;
        As[acol + 2][arow] = av.z;
        As[acol + 3][arow] = av.w;
        *(float4*)(&Bs[brow][bcol]) = bv4;
        __syncthreads();
        #pragma unroll
        for (int k = 0; k < 8; k++) {
            float a[8], b[8];
            #pragma unroll
            for (int i = 0; i < 8; i++) a[i] = As[k][tr * 8 + i];
            #pragma unroll
            for (int j = 0; j < 8; j++) b[j] = Bs[k][tc * 8 + j];
            #pragma unroll
            for (int i = 0; i < 8; i++)
                #pragma unroll
                for (int j = 0; j < 8; j++)
                    acc[i][j] = fmaf(a[i], b[j], acc[i][j]);
        }
    }

    // Epilogue: write into head-split scratch [z][b*H+h][t][hd]
    const int bidx = bm >> 4;   // 128-row tiles: 16 tiles per batch (T=2048)
    #pragma unroll
    for (int i = 0; i < 8; i++) {
        int m = bm * 128 + tr * 8 + i;
        int t = m & (TT - 1);
        #pragma unroll
        for (int j = 0; j < 8; j++) {
            int col = bn * 128 + tc * 8 + j;
            int h  = col >> 6;
            int hd = col & 63;
            g_qkv[(((size_t)z * BHH + bidx * HH + h) * TT + t) * HDD + hd] =
                acc[i][j] + bias[col];
        }
    }
}

// ---------------------------------------------------------------------------
// Flash attention: one block = one (b,h) and 64 query rows.
// Loops over 32-key tiles with online softmax. O accumulated in registers.
// Thread layout: 16x16; each thread owns 4 query rows.
//   S pass:  s[4 rows][2 key cols]   (64x32 S tile)
//   PV pass: o[4 rows][4 hd cols]    (64x64 O tile)
// ---------------------------------------------------------------------------
__global__ void __launch_bounds__(256) attn_kernel(float* __restrict__ out)
{
    __shared__ float Qs[64 * 64];    // Q tile, pre-scaled, stride 64
    __shared__ float KPs[32 * 65];   // K tile (stride 65), reused as P (stride 32)
    __shared__ float Vs[32 * 64];    // V tile, stride 64

    const int tid = threadIdx.x;
    const int ty = tid >> 4;   // 0..15 -> query rows ty*4..ty*4+3
    const int tx = tid & 15;   // 0..15
    const int bh = blockIdx.y;
    const int q0 = blockIdx.x * 64;

    const float* Qg = g_qkv + ((size_t)(0 * BHH + bh) * TT + q0) * HDD;
    const float* Kg = g_qkv + ((size_t)(1 * BHH + bh) * TT) * HDD;
    const float* Vg = g_qkv + ((size_t)(2 * BHH + bh) * TT) * HDD;

    const float scale = 0.125f;   // 1/sqrt(64)

    // Load Q tile once, pre-scaled.
    for (int i = tid; i < 64 * 16; i += 256) {
        int r = i >> 4, c4 = (i & 15) * 4;
        float4 v = *(const float4*)(Qg + (size_t)r * 64 + c4);
        Qs[r * 64 + c4 + 0] = v.x * scale;
        Qs[r * 64 + c4 + 1] = v.y * scale;
        Qs[r * 64 + c4 + 2] = v.z * scale;
        Qs[r * 64 + c4 + 3] = v.w * scale;
    }

    float m_[4], l_[4];
    float o[4][4] = {};
    #pragma unroll
    for (int i = 0; i < 4; i++) { m_[i] = -1e30f; l_[i] = 0.f; }

    for (int jt = 0; jt < TT / 32; jt++) {
        __syncthreads();   // prior PV pass done; safe to overwrite KPs/Vs
        // Load K tile (stride 65) and V tile (stride 64)
        for (int i = tid; i < 32 * 16; i += 256) {
            int r = i >> 4, c4 = (i & 15) * 4;
            float4 kv = *(const float4*)(Kg + (size_t)(jt * 32 + r) * 64 + c4);
            KPs[r * 65 + c4 + 0] = kv.x;
            KPs[r * 65 + c4 + 1] = kv.y;
            KPs[r * 65 + c4 + 2] = kv.z;
            KPs[r * 65 + c4 + 3] = kv.w;
            float4 vv = *(const float4*)(Vg + (size_t)(jt * 32 + r) * 64 + c4);
            *(float4*)(&Vs[r * 64 + c4]) = vv;
        }
        __syncthreads();

        // S = (Q*scale) @ K^T : 64x32 tile, 4x2 per thread
        float s[4][2] = {};
        #pragma unroll 8
        for (int d = 0; d < 64; d++) {
            float q[4], k2[2];
            #pragma unroll
            for (int i = 0; i < 4; i++) q[i] = Qs[(ty * 4 + i) * 64 + d];
            #pragma unroll
            for (int j = 0; j < 2; j++) k2[j] = KPs[(tx * 2 + j) * 65 + d];
            #pragma unroll
            for (int i = 0; i < 4; i++)
                #pragma unroll
                for (int j = 0; j < 2; j++)
                    s[i][j] = fmaf(q[i], k2[j], s[i][j]);
        }

        // Online softmax: row stats shared by 16 tx threads (shfl width 16)
        float p[4][2];
        #pragma unroll
        for (int i = 0; i < 4; i++) {
            float mx = fmaxf(s[i][0], s[i][1]);
            #pragma unroll
            for (int off = 8; off > 0; off >>= 1)
                mx = fmaxf(mx, __shfl_xor_sync(0xffffffffu, mx, off, 16));
            float mnew  = fmaxf(m_[i], mx);
            float alpha = __expf(m_[i] - mnew);
            float ps = 0.f;
            #pragma unroll
            for (int j = 0; j < 2; j++) {
                p[i][j] = __expf(s[i][j] - mnew);
                ps += p[i][j];
            }
            #pragma unroll
            for (int off = 8; off > 0; off >>= 1)
                ps += __shfl_xor_sync(0xffffffffu, ps, off, 16);
            l_[i] = l_[i] * alpha + ps;
            m_[i] = mnew;
            #pragma unroll
            for (int j = 0; j < 4; j++) o[i][j] *= alpha;
        }

        __syncthreads();   // everyone done reading K rows before P overwrite
        // Write P (64x32, stride 32) into KPs
        #pragma unroll
        for (int i = 0; i < 4; i++)
            #pragma unroll
            for (int j = 0; j < 2; j++)
                KPs[(ty * 4 + i) * 32 + tx * 2 + j] = p[i][j];
        __syncthreads();

        // O += P @ V : 64x64, 4x4 per thread
        #pragma unroll 4
        for (int k = 0; k < 32; k++) {
            float pp[4], vv[4];
            #pragma unroll
            for (int i = 0; i < 4; i++) pp[i] = KPs[(ty * 4 + i) * 32 + k];
            #pragma unroll
            for (int j = 0; j < 4; j++) vv[j] = Vs[k * 64 + tx * 4 + j];
            #pragma unroll
            for (int i = 0; i < 4; i++)
                #pragma unroll
                for (int j = 0; j < 4; j++)
                    o[i][j] = fmaf(pp[i], vv[j], o[i][j]);
        }
    }

    // Normalize and write out in [B][T][D] layout
    const int b = bh >> 4, h = bh & 15;
    #pragma unroll
    for (int i = 0; i < 4; i++) {
        float inv = 1.0f / l_[i];
        int t = q0 + ty * 4 + i;
        #pragma unroll
        for (int j = 0; j < 4; j++) {
            int col = h * 64 + tx * 4 + j;
            out[((size_t)b * TT + t) * DD + col] = o[i][j] * inv;
        }
    }
}

// ---------------------------------------------------------------------------
extern "C" void kernel_launch(void* const* d_in, const int* in_sizes, int n_in,
                              void* d_out, int out_size)
{
    const float* x  = (const float*)d_in[0];
    const float* Wq = (const float*)d_in[1];
    const float* bq = (const float*)d_in[2];
    const float* Wk = (const float*)d_in[3];
    const float* bk = (const float*)d_in[4];
    const float* Wv = (const float*)d_in[5];
    const float* bv = (const float*)d_in[6];
    float* out = (float*)d_out;

    // QKV projections: grid (N/128, M/128, 3)
    qkv_gemm_kernel<<<dim3(DD / 128, BB * TT / 128, 3), 256>>>(
        x, Wq, bq, Wk, bk, Wv, bv);

    // Attention: grid (T/64 query tiles, B*H heads)
    attn_kernel<<<dim3(TT / 64, BHH), 256>>>(out);
}